// round 7
// baseline (speedup 1.0000x reference)
#include <cuda_runtime.h>

#define FIN 128
#define HD  128
#define C3  384
#define H1D 256
#define OUTD 40
#define NMAX 50000
#define EMAX 800000

// ---------------- scratch (static device globals; no allocation allowed) ----
__device__ __align__(16) float g_H[(size_t)NMAX * C3];     // [x@Wgat | x@Wgcn | x@Wsage_r]
__device__ __align__(16) float g_hcat[(size_t)NMAX * C3];  // [gat_out | gcn_out | sage_out]
__device__ __align__(16) float g_sage[(size_t)NMAX * HD];  // mean of x over in-neighbors
__device__ __align__(16) float g_h1[(size_t)NMAX * H1D];
__device__ __align__(16) float g_h2[(size_t)NMAX * HD];
__device__ __align__(16) float g_Wcat[FIN * C3];           // [W_gat|W_gcn|W_sage_r]
__device__ __align__(16) float4 g_csr[EMAX];               // {src, wg, wc, -}
__device__ float g_as[NMAX], g_ad[NMAX], g_m[NMAX], g_dinv[NMAX], g_es[NMAX];
__device__ int   g_mint[NMAX], g_deg[NMAX], g_cnt[NMAX];
__device__ int   g_off[NMAX + 1], g_cur[NMAX];
__device__ float g_sums[C3], g_sumsq[C3], g_scale[C3], g_shift[C3];
__device__ int   g_is64;   // 1 if edge_index buffer is int64, 0 if int32

// device-side scratch-buffer resolver (host never needs the addresses)
#define TAG_NONE  (-1)
#define TAG_H     0
#define TAG_HCAT  1
#define TAG_SAGE  2
#define TAG_H1    3
#define TAG_H2    4
#define TAG_WCAT  5
__device__ __forceinline__ float* buf(int tag) {
    switch (tag) {
        case TAG_H:    return g_H;
        case TAG_HCAT: return g_hcat;
        case TAG_SAGE: return g_sage;
        case TAG_H1:   return g_h1;
        case TAG_H2:   return g_h2;
        case TAG_WCAT: return g_Wcat;
    }
    return nullptr;
}

__device__ __forceinline__ float leaky(float x) { return x > 0.f ? x : 0.2f * x; }
// order-preserving float->int key for atomicMax
__device__ __forceinline__ int   encf(float f) { int i = __float_as_int(f); return i >= 0 ? i : (i ^ 0x7FFFFFFF); }
__device__ __forceinline__ float decf(int i)   { return __int_as_float(i >= 0 ? i : (i ^ 0x7FFFFFFF)); }

// edge-index accessor robust to int32-vs-int64 storage
__device__ __forceinline__ int ld_idx(const void* ei, size_t i) {
    if (g_is64) return (int)((const long long*)ei)[i];
    return ((const int*)ei)[i];
}

// ---------------- dtype detect: odd 32-bit words all zero  <=>  int64 -------
__global__ void detect_idx(const void* ei, int E)
{
    const int* w = (const int*)ei;
    int n = E < 128 ? E : 128;
    int t = threadIdx.x;            // 128 threads
    int nz = 0;
    if (t < n) nz = (w[2 * t + 1] != 0) ? 1 : 0;
    #pragma unroll
    for (int o = 16; o; o >>= 1) nz += __shfl_xor_sync(0xffffffffu, nz, o);
    __shared__ int sh[4];
    if ((t & 31) == 0) sh[t >> 5] = nz;
    __syncthreads();
    if (t == 0) g_is64 = ((sh[0] + sh[1] + sh[2] + sh[3]) == 0) ? 1 : 0;
}

// ---------------- pack B = [W_gat | W_gcn | W_sage_r] ------------------------
__global__ void pack_w(const float* __restrict__ a, const float* __restrict__ b,
                       const float* __restrict__ c)
{
    int i = blockIdx.x * blockDim.x + threadIdx.x;
    if (i >= FIN * C3) return;
    int k = i / C3, j = i % C3;
    float v;
    if (j < 128)      v = a[k * HD + j];
    else if (j < 256) v = b[k * HD + j - 128];
    else              v = c[k * HD + j - 256];
    g_Wcat[i] = v;
}

// ---------------- node init: a_src/a_dst dots, seeds ------------------------
__global__ void node_init(const float* __restrict__ att_s,
                          const float* __restrict__ att_d, int N)
{
    int gw   = (blockIdx.x * blockDim.x + threadIdx.x) >> 5;
    int lane = threadIdx.x & 31;
    if (gw >= N) return;
    float4 h = ((const float4*)(g_H + (size_t)gw * C3))[lane];   // first 128 = gat h
    float4 s = ((const float4*)att_s)[lane];
    float4 d = ((const float4*)att_d)[lane];
    float ps = h.x * s.x + h.y * s.y + h.z * s.z + h.w * s.w;
    float pd = h.x * d.x + h.y * d.y + h.z * d.z + h.w * d.w;
    #pragma unroll
    for (int o = 16; o; o >>= 1) {
        ps += __shfl_xor_sync(0xffffffffu, ps, o);
        pd += __shfl_xor_sync(0xffffffffu, pd, o);
    }
    if (lane == 0) {
        g_as[gw] = ps; g_ad[gw] = pd;
        g_mint[gw] = encf(leaky(ps + pd));  // self-loop seeds segment max
        g_deg[gw] = 1;                      // self loop counts for GCN degree
        g_cnt[gw] = 0;                      // SAGE/CSR in-degree (no self loops)
    }
}

// ---------------- edge pass 1: max / degree / count -------------------------
__global__ void edge_pass1(const void* __restrict__ ei, int E)
{
    int e = blockIdx.x * blockDim.x + threadIdx.x;
    if (e >= E) return;
    int s = ld_idx(ei, e);
    int d = ld_idx(ei, (size_t)E + e);
    float ev = leaky(g_as[s] + g_ad[d]);
    atomicMax(&g_mint[d], encf(ev));
    atomicAdd(&g_deg[d], 1);
    atomicAdd(&g_cnt[d], 1);
}

// ---------------- node scalars: m, es, dinv ---------------------------------
__global__ void node_seed(int N)
{
    int i = blockIdx.x * blockDim.x + threadIdx.x;
    if (i >= N) return;
    float m = decf(g_mint[i]);
    g_m[i]    = m;
    g_es[i]   = expf(leaky(g_as[i] + g_ad[i]) - m);
    g_dinv[i] = rsqrtf((float)g_deg[i]);
}

// ---------------- exclusive scan of cnt -> off, cur (single block) ----------
__global__ void scan_cnt(int N, int E)
{
    __shared__ int part[1024];
    int t = threadIdx.x;
    int chunk = (N + 1023) / 1024;
    int lo = t * chunk;
    int hi = lo + chunk; if (hi > N) hi = N;
    int s = 0;
    for (int i = lo; i < hi; i++) s += g_cnt[i];
    part[t] = s;
    __syncthreads();
    for (int o = 1; o < 1024; o <<= 1) {
        int v = (t >= o) ? part[t - o] : 0;
        __syncthreads();
        part[t] += v;
        __syncthreads();
    }
    int base = (t == 0) ? 0 : part[t - 1];
    for (int i = lo; i < hi; i++) {
        g_off[i] = base;
        g_cur[i] = base;
        base += g_cnt[i];
    }
    if (t == 0) g_off[N] = E;
}

// ---------------- fill CSR: per-edge meta {src, wg, wc} ---------------------
__global__ void edge_fill(const void* __restrict__ ei, int E)
{
    int e = blockIdx.x * blockDim.x + threadIdx.x;
    if (e >= E) return;
    int s = ld_idx(ei, e);
    int d = ld_idx(ei, (size_t)E + e);
    float wg = expf(leaky(g_as[s] + g_ad[d]) - g_m[d]);
    float wc = g_dinv[s] * g_dinv[d];
    int pos = atomicAdd(&g_cur[d], 1);
    g_csr[pos] = make_float4(__int_as_float(s), wg, wc, 0.f);
}

// ---------------- gather: one warp per dst node (no float atomics) ----------
__global__ void gather(const float* __restrict__ x,
                       const float* __restrict__ bg,
                       const float* __restrict__ bc, int N)
{
    int gw   = (blockIdx.x * blockDim.x + threadIdx.x) >> 5;
    int lane = threadIdx.x & 31;
    if (gw >= N) return;

    const float4* hr = (const float4*)(g_H + (size_t)gw * C3);
    float es   = g_es[gw];
    float dinv = g_dinv[gw];
    float d2   = dinv * dinv;

    // self-loop seeds
    float4 hg = hr[lane];
    float4 hc = hr[lane + 32];
    float ag0 = es * hg.x, ag1 = es * hg.y, ag2 = es * hg.z, ag3 = es * hg.w;
    float ac0 = d2 * hc.x, ac1 = d2 * hc.y, ac2 = d2 * hc.z, ac3 = d2 * hc.w;
    float ax0 = 0.f, ax1 = 0.f, ax2 = 0.f, ax3 = 0.f;
    float denom = es;

    int lo = g_off[gw], hi = g_off[gw + 1];
    for (int j = lo; j < hi; j++) {
        float4 meta;
        if (lane == 0) meta = g_csr[j];
        int   s  = __shfl_sync(0xffffffffu, __float_as_int(meta.x), 0);
        float wg = __shfl_sync(0xffffffffu, meta.y, 0);
        float wc = __shfl_sync(0xffffffffu, meta.z, 0);
        const float4* hs = (const float4*)(g_H + (size_t)s * C3);
        float4 vg = hs[lane];
        float4 vc = hs[lane + 32];
        float4 vx = ((const float4*)(x + (size_t)s * FIN))[lane];
        ag0 = fmaf(wg, vg.x, ag0); ag1 = fmaf(wg, vg.y, ag1);
        ag2 = fmaf(wg, vg.z, ag2); ag3 = fmaf(wg, vg.w, ag3);
        ac0 = fmaf(wc, vc.x, ac0); ac1 = fmaf(wc, vc.y, ac1);
        ac2 = fmaf(wc, vc.z, ac2); ac3 = fmaf(wc, vc.w, ac3);
        ax0 += vx.x; ax1 += vx.y; ax2 += vx.z; ax3 += vx.w;
        denom += wg;
    }

    float inv = 1.f / denom;
    float ci  = 1.f / fmaxf((float)(hi - lo), 1.f);
    float4 b  = ((const float4*)bg)[lane];
    float4 b2 = ((const float4*)bc)[lane];
    float4* oc = (float4*)(g_hcat + (size_t)gw * C3);
    oc[lane]      = make_float4(ag0 * inv + b.x,  ag1 * inv + b.y,
                                ag2 * inv + b.z,  ag3 * inv + b.w);
    oc[lane + 32] = make_float4(ac0 + b2.x, ac1 + b2.y, ac2 + b2.z, ac3 + b2.w);
    ((float4*)(g_sage + (size_t)gw * HD))[lane] =
        make_float4(ax0 * ci, ax1 * ci, ax2 * ci, ax3 * ci);
}

// ---------------- BatchNorm stats ------------------------------------------
__global__ void bn_zero()
{
    int t = threadIdx.x;
    if (t < C3) { g_sums[t] = 0.f; g_sumsq[t] = 0.f; }
}

__global__ void bn_stats(int N)
{
    int c = blockIdx.x * 32 + threadIdx.x;
    float s = 0.f, q = 0.f;
    for (int r = blockIdx.y * blockDim.y + threadIdx.y; r < N; r += gridDim.y * blockDim.y) {
        float v = g_hcat[(size_t)r * C3 + c];
        s += v; q += v * v;
    }
    __shared__ float sh[8][33], shq[8][33];
    sh[threadIdx.y][threadIdx.x] = s;
    shq[threadIdx.y][threadIdx.x] = q;
    __syncthreads();
    if (threadIdx.y == 0) {
        #pragma unroll
        for (int j = 1; j < 8; j++) { s += sh[j][threadIdx.x]; q += shq[j][threadIdx.x]; }
        atomicAdd(&g_sums[c], s);
        atomicAdd(&g_sumsq[c], q);
    }
}

__global__ void bn_scale(const float* __restrict__ gamma,
                         const float* __restrict__ beta, int N)
{
    int c = threadIdx.x;
    if (c >= C3) return;
    float invN = 1.f / (float)N;
    float mu  = g_sums[c] * invN;
    float var = g_sumsq[c] * invN - mu * mu;
    float sc  = gamma[c] * rsqrtf(var + 1e-5f);
    g_scale[c] = sc;
    g_shift[c] = beta[c] - mu * sc;
}

// ---------------- 128x128-tile fp32 GEMM, 8x8 micro-tile --------------------
// C[M,Nc] = act(A[M,K]) @ B[K,Nc] (+bias) (+Dadd)
// MODE 0: identity ; MODE 1: relu(A) ; MODE 2: relu(A*g_scale[k]+g_shift[k])
template<int MODE>
__global__ void __launch_bounds__(256) gemm2(
    const float* __restrict__ Aext, int Atag, int Aoff, int lda,
    const float* __restrict__ Bext, int Btag, int ldb,
    float* __restrict__ Cext, int Ctag, int Coff, int ldc,
    int M, int Nc, int K,
    const float* __restrict__ bias,
    int Dtag, int Doff, int ldd)
{
    const float* A = Aext ? Aext : (const float*)(buf(Atag) + Aoff);
    const float* B = Bext ? Bext : (const float*)buf(Btag);
    float*       C = Cext ? Cext : (buf(Ctag) + Coff);
    const float* Dadd = (Dtag >= 0) ? (const float*)(buf(Dtag) + Doff) : nullptr;

    __shared__ float As[16][128];
    __shared__ float Bs[16][128];
    const int t = threadIdx.x;
    const int rowBase = blockIdx.x * 128;
    const int colBase = blockIdx.y * 128;
    const int ty = t >> 4, tx = t & 15;     // 16x16 thread grid, 8x8 each

    float acc[8][8];
    #pragma unroll
    for (int m = 0; m < 8; m++)
        #pragma unroll
        for (int n = 0; n < 8; n++) acc[m][n] = 0.f;

    for (int k0 = 0; k0 < K; k0 += 16) {
        // load A tile 128x16 (transposed into As[k][r]); 512 float4, 2/thread
        #pragma unroll
        for (int i = 0; i < 2; i++) {
            int idx = t + i * 256;
            int r   = idx >> 2;
            int kc  = (idx & 3) << 2;
            int grow = rowBase + r;
            float4 v = make_float4(0.f, 0.f, 0.f, 0.f);
            if (grow < M) v = *(const float4*)(A + (size_t)grow * lda + k0 + kc);
            if (MODE == 1) {
                v.x = fmaxf(v.x, 0.f); v.y = fmaxf(v.y, 0.f);
                v.z = fmaxf(v.z, 0.f); v.w = fmaxf(v.w, 0.f);
            }
            if (MODE == 2) {
                v.x = fmaxf(v.x * g_scale[k0 + kc + 0] + g_shift[k0 + kc + 0], 0.f);
                v.y = fmaxf(v.y * g_scale[k0 + kc + 1] + g_shift[k0 + kc + 1], 0.f);
                v.z = fmaxf(v.z * g_scale[k0 + kc + 2] + g_shift[k0 + kc + 2], 0.f);
                v.w = fmaxf(v.w * g_scale[k0 + kc + 3] + g_shift[k0 + kc + 3], 0.f);
            }
            As[kc + 0][r] = v.x; As[kc + 1][r] = v.y;
            As[kc + 2][r] = v.z; As[kc + 3][r] = v.w;
        }
        // load B tile 16x128; 512 float4, 2/thread
        #pragma unroll
        for (int i = 0; i < 2; i++) {
            int idx = t + i * 256;
            int kr  = idx >> 5;
            int c4  = (idx & 31) << 2;
            int gc  = colBase + c4;
            float4 v = make_float4(0.f, 0.f, 0.f, 0.f);
            if (gc < Nc) v = *(const float4*)(B + (size_t)(k0 + kr) * ldb + gc);
            *(float4*)&Bs[kr][c4] = v;
        }
        __syncthreads();
        #pragma unroll
        for (int k = 0; k < 16; k++) {
            float a[8], b[8];
            *(float4*)&a[0] = *(const float4*)&As[k][ty * 8];
            *(float4*)&a[4] = *(const float4*)&As[k][ty * 8 + 4];
            *(float4*)&b[0] = *(const float4*)&Bs[k][tx * 8];
            *(float4*)&b[4] = *(const float4*)&Bs[k][tx * 8 + 4];
            #pragma unroll
            for (int m = 0; m < 8; m++)
                #pragma unroll
                for (int n = 0; n < 8; n++)
                    acc[m][n] = fmaf(a[m], b[n], acc[m][n]);
        }
        __syncthreads();
    }
    #pragma unroll
    for (int m = 0; m < 8; m++) {
        int gr = rowBase + ty * 8 + m;
        if (gr >= M) continue;
        #pragma unroll
        for (int n = 0; n < 8; n++) {
            int gc = colBase + tx * 8 + n;
            if (gc >= Nc) continue;
            float v = acc[m][n];
            if (bias) v += bias[gc];
            if (Dadd) v += Dadd[(size_t)gr * ldd + gc];
            C[(size_t)gr * ldc + gc] = v;
        }
    }
}

// ---------------- launch ----------------------------------------------------
extern "C" void kernel_launch(void* const* d_in, const int* in_sizes, int n_in,
                              void* d_out, int out_size)
{
    const float* x        = (const float*)d_in[0];
    const void*  ei       = d_in[1];
    const float* W_gat    = (const float*)d_in[2];
    const float* att_src  = (const float*)d_in[3];
    const float* att_dst  = (const float*)d_in[4];
    const float* b_gat    = (const float*)d_in[5];
    const float* W_gcn    = (const float*)d_in[6];
    const float* b_gcn    = (const float*)d_in[7];
    const float* W_sage_l = (const float*)d_in[8];
    const float* b_sage_l = (const float*)d_in[9];
    const float* W_sage_r = (const float*)d_in[10];
    const float* W1       = (const float*)d_in[11];
    const float* b1       = (const float*)d_in[12];
    const float* W2       = (const float*)d_in[13];
    const float* b2       = (const float*)d_in[14];
    const float* W3       = (const float*)d_in[15];
    const float* b3       = (const float*)d_in[16];
    const float* gamma    = (const float*)d_in[17];
    const float* beta     = (const float*)d_in[18];
    float* out = (float*)d_out;

    int N = in_sizes[0] / FIN;
    int E = in_sizes[1] / 2;

    // 0) detect edge_index storage width (int32 vs int64); pack node-GEMM B
    detect_idx<<<1, 128>>>(ei, E);
    pack_w<<<(FIN * C3 + 255) / 256, 256>>>(W_gat, W_gcn, W_sage_r);

    int gm = (N + 127) / 128;

    // 1) H = x @ [W_gat | W_gcn | W_sage_r]  (one merged GEMM, Nc=384)
    gemm2<0><<<dim3(gm, 3), 256>>>(x, TAG_NONE, 0, FIN, nullptr, TAG_WCAT, C3,
                                   nullptr, TAG_H, 0, C3, N, C3, FIN,
                                   nullptr, TAG_NONE, 0, 0);

    // 2-6) graph aggregation via CSR gather
    node_init<<<(N + 7) / 8, 256>>>(att_src, att_dst, N);
    edge_pass1<<<(E + 255) / 256, 256>>>(ei, E);
    node_seed<<<(N + 255) / 256, 256>>>(N);
    scan_cnt<<<1, 1024>>>(N, E);
    edge_fill<<<(E + 255) / 256, 256>>>(ei, E);
    gather<<<(N + 7) / 8, 256>>>(x, b_gat, b_gcn, N);

    // 7) sage: hcat[:,256:384] = mean @ W_sage_l + b_sage_l + (x@W_sage_r)
    gemm2<0><<<dim3(gm, 1), 256>>>(nullptr, TAG_SAGE, 0, HD, W_sage_l, TAG_NONE, HD,
                                   nullptr, TAG_HCAT, 256, C3, N, HD, HD,
                                   b_sage_l, TAG_H, 256, C3);

    // 8-9) batchnorm statistics -> per-channel scale/shift
    bn_zero<<<1, 384>>>();
    dim3 bs(32, 8), bg(C3 / 32, 128);
    bn_stats<<<bg, bs>>>(N);
    bn_scale<<<1, 384>>>(gamma, beta, N);

    // 10-12) MLP (BN affine + relu fused into W1 A-load; relu fused into later loads)
    gemm2<2><<<dim3(gm, 2), 256>>>(nullptr, TAG_HCAT, 0, C3, W1, TAG_NONE, H1D,
                                   nullptr, TAG_H1, 0, H1D, N, H1D, C3,
                                   b1, TAG_NONE, 0, 0);
    gemm2<1><<<dim3(gm, 1), 256>>>(nullptr, TAG_H1, 0, H1D, W2, TAG_NONE, HD,
                                   nullptr, TAG_H2, 0, HD, N, HD, H1D,
                                   b2, TAG_NONE, 0, 0);
    gemm2<1><<<dim3(gm, 1), 256>>>(nullptr, TAG_H2, 0, HD, W3, TAG_NONE, OUTD,
                                   out, TAG_NONE, 0, OUTD, N, OUTD, HD,
                                   b3, TAG_NONE, 0, 0);
}

// round 8
// speedup vs baseline: 1.8133x; 1.8133x over previous
#include <cuda_runtime.h>

#define FIN 128
#define HD  128
#define C3  384
#define H1D 256
#define OUTD 40
#define NMAX 50000
#define EMAX 800000

// ---------------- scratch (static device globals; no allocation allowed) ----
__device__ __align__(16) float g_H[(size_t)NMAX * C3];     // [x@Wgat | x@Wgcn | x@Wsage_r]
__device__ __align__(16) float g_hcat[(size_t)NMAX * C3];  // [gat_out | gcn_out | sage_out]
__device__ __align__(16) float g_sage[(size_t)NMAX * HD];  // mean of x over in-neighbors
__device__ __align__(16) float g_h1[(size_t)NMAX * H1D];
__device__ __align__(16) float g_h2[(size_t)NMAX * HD];
__device__ __align__(16) float g_Wcat[FIN * C3];           // [W_gat|W_gcn|W_sage_r]
__device__ __align__(16) float4 g_csr[EMAX];               // {src, wg, wc, -}
__device__ float g_as[NMAX], g_ad[NMAX], g_m[NMAX], g_dinv[NMAX], g_es[NMAX];
__device__ int   g_mint[NMAX], g_deg[NMAX];
__device__ int   g_off[NMAX + 1], g_cur[NMAX];
__device__ float g_sums[C3], g_sumsq[C3], g_scale[C3], g_shift[C3];
__device__ int   g_is64;   // 1 if edge_index buffer is int64, 0 if int32

// device-side scratch-buffer resolver (host never needs the addresses)
#define TAG_NONE  (-1)
#define TAG_H     0
#define TAG_HCAT  1
#define TAG_SAGE  2
#define TAG_H1    3
#define TAG_H2    4
#define TAG_WCAT  5
__device__ __forceinline__ float* buf(int tag) {
    switch (tag) {
        case TAG_H:    return g_H;
        case TAG_HCAT: return g_hcat;
        case TAG_SAGE: return g_sage;
        case TAG_H1:   return g_h1;
        case TAG_H2:   return g_h2;
        case TAG_WCAT: return g_Wcat;
    }
    return nullptr;
}

__device__ __forceinline__ float leaky(float x) { return x > 0.f ? x : 0.2f * x; }
// order-preserving float->int key for atomicMax
__device__ __forceinline__ int   encf(float f) { int i = __float_as_int(f); return i >= 0 ? i : (i ^ 0x7FFFFFFF); }
__device__ __forceinline__ float decf(int i)   { return __int_as_float(i >= 0 ? i : (i ^ 0x7FFFFFFF)); }

// edge-index accessor robust to int32-vs-int64 storage
__device__ __forceinline__ int ld_idx(const void* ei, size_t i) {
    if (g_is64) return (int)((const long long*)ei)[i];
    return ((const int*)ei)[i];
}

// ---------------- dtype detect: odd 32-bit words all zero  <=>  int64 -------
__global__ void detect_idx(const void* ei, int E)
{
    const int* w = (const int*)ei;
    int n = E < 128 ? E : 128;
    int t = threadIdx.x;            // 128 threads
    int nz = 0;
    if (t < n) nz = (w[2 * t + 1] != 0) ? 1 : 0;
    #pragma unroll
    for (int o = 16; o; o >>= 1) nz += __shfl_xor_sync(0xffffffffu, nz, o);
    __shared__ int sh[4];
    if ((t & 31) == 0) sh[t >> 5] = nz;
    __syncthreads();
    if (t == 0) g_is64 = ((sh[0] + sh[1] + sh[2] + sh[3]) == 0) ? 1 : 0;
}

// ---------------- pack B = [W_gat | W_gcn | W_sage_r] ------------------------
__global__ void pack_w(const float* __restrict__ a, const float* __restrict__ b,
                       const float* __restrict__ c)
{
    int i = blockIdx.x * blockDim.x + threadIdx.x;
    if (i >= FIN * C3) return;
    int k = i / C3, j = i % C3;
    float v;
    if (j < 128)      v = a[k * HD + j];
    else if (j < 256) v = b[k * HD + j - 128];
    else              v = c[k * HD + j - 256];
    g_Wcat[i] = v;
}

// ---------------- node init: a_src/a_dst dots, seeds ------------------------
__global__ void node_init(const float* __restrict__ att_s,
                          const float* __restrict__ att_d, int N)
{
    int gw   = (blockIdx.x * blockDim.x + threadIdx.x) >> 5;
    int lane = threadIdx.x & 31;
    if (gw >= N) return;
    float4 h = ((const float4*)(g_H + (size_t)gw * C3))[lane];   // first 128 = gat h
    float4 s = ((const float4*)att_s)[lane];
    float4 d = ((const float4*)att_d)[lane];
    float ps = h.x * s.x + h.y * s.y + h.z * s.z + h.w * s.w;
    float pd = h.x * d.x + h.y * d.y + h.z * d.z + h.w * d.w;
    #pragma unroll
    for (int o = 16; o; o >>= 1) {
        ps += __shfl_xor_sync(0xffffffffu, ps, o);
        pd += __shfl_xor_sync(0xffffffffu, pd, o);
    }
    if (lane == 0) {
        g_as[gw] = ps; g_ad[gw] = pd;
        g_mint[gw] = encf(leaky(ps + pd));  // self-loop seeds segment max
        g_deg[gw] = 1;                      // self loop counts for GCN degree
    }
}

// ---------------- edge pass 1: max / degree ---------------------------------
__global__ void edge_pass1(const void* __restrict__ ei, int E)
{
    int e = blockIdx.x * blockDim.x + threadIdx.x;
    if (e >= E) return;
    int s = ld_idx(ei, e);
    int d = ld_idx(ei, (size_t)E + e);
    float ev = leaky(g_as[s] + g_ad[d]);
    atomicMax(&g_mint[d], encf(ev));
    atomicAdd(&g_deg[d], 1);     // in-degree+1; CSR count = deg-1
}

// ---------------- node scalars: m, es, dinv ---------------------------------
__global__ void node_seed(int N)
{
    int i = blockIdx.x * blockDim.x + threadIdx.x;
    if (i >= N) return;
    float m = decf(g_mint[i]);
    g_m[i]    = m;
    g_es[i]   = expf(leaky(g_as[i] + g_ad[i]) - m);
    g_dinv[i] = rsqrtf((float)g_deg[i]);
}

// ---------------- exclusive scan of (deg-1) -> off, cur (single block) ------
__global__ void scan_cnt(int N, int E)
{
    __shared__ int part[1024];
    int t = threadIdx.x;
    int chunk = (N + 1023) / 1024;
    int lo = t * chunk;
    int hi = lo + chunk; if (hi > N) hi = N;
    int s = 0;
    for (int i = lo; i < hi; i++) s += g_deg[i] - 1;
    part[t] = s;
    __syncthreads();
    for (int o = 1; o < 1024; o <<= 1) {
        int v = (t >= o) ? part[t - o] : 0;
        __syncthreads();
        part[t] += v;
        __syncthreads();
    }
    int base = (t == 0) ? 0 : part[t - 1];
    for (int i = lo; i < hi; i++) {
        g_off[i] = base;
        g_cur[i] = base;
        base += g_deg[i] - 1;
    }
    if (t == 0) g_off[N] = E;
}

// ---------------- fill CSR: per-edge meta {src, wg, wc} ---------------------
__global__ void edge_fill(const void* __restrict__ ei, int E)
{
    int e = blockIdx.x * blockDim.x + threadIdx.x;
    if (e >= E) return;
    int s = ld_idx(ei, e);
    int d = ld_idx(ei, (size_t)E + e);
    float wg = expf(leaky(g_as[s] + g_ad[d]) - g_m[d]);
    float wc = g_dinv[s] * g_dinv[d];
    int pos = atomicAdd(&g_cur[d], 1);
    g_csr[pos] = make_float4(__int_as_float(s), wg, wc, 0.f);
}

// ---------------- gather: one warp per dst node (no float atomics) ----------
__global__ void gather(const float* __restrict__ x,
                       const float* __restrict__ bg,
                       const float* __restrict__ bc, int N)
{
    int gw   = (blockIdx.x * blockDim.x + threadIdx.x) >> 5;
    int lane = threadIdx.x & 31;
    if (gw >= N) return;

    const float4* hr = (const float4*)(g_H + (size_t)gw * C3);
    float es   = g_es[gw];
    float dinv = g_dinv[gw];
    float d2   = dinv * dinv;

    // self-loop seeds
    float4 hg = hr[lane];
    float4 hc = hr[lane + 32];
    float ag0 = es * hg.x, ag1 = es * hg.y, ag2 = es * hg.z, ag3 = es * hg.w;
    float ac0 = d2 * hc.x, ac1 = d2 * hc.y, ac2 = d2 * hc.z, ac3 = d2 * hc.w;
    float ax0 = 0.f, ax1 = 0.f, ax2 = 0.f, ax3 = 0.f;
    float denom = es;

    int lo = g_off[gw], hi = g_off[gw + 1];
    for (int j = lo; j < hi; j++) {
        float4 meta;
        if (lane == 0) meta = g_csr[j];
        int   s  = __shfl_sync(0xffffffffu, __float_as_int(meta.x), 0);
        float wg = __shfl_sync(0xffffffffu, meta.y, 0);
        float wc = __shfl_sync(0xffffffffu, meta.z, 0);
        const float4* hs = (const float4*)(g_H + (size_t)s * C3);
        float4 vg = hs[lane];
        float4 vc = hs[lane + 32];
        float4 vx = ((const float4*)(x + (size_t)s * FIN))[lane];
        ag0 = fmaf(wg, vg.x, ag0); ag1 = fmaf(wg, vg.y, ag1);
        ag2 = fmaf(wg, vg.z, ag2); ag3 = fmaf(wg, vg.w, ag3);
        ac0 = fmaf(wc, vc.x, ac0); ac1 = fmaf(wc, vc.y, ac1);
        ac2 = fmaf(wc, vc.z, ac2); ac3 = fmaf(wc, vc.w, ac3);
        ax0 += vx.x; ax1 += vx.y; ax2 += vx.z; ax3 += vx.w;
        denom += wg;
    }

    float inv = 1.f / denom;
    float ci  = 1.f / fmaxf((float)(hi - lo), 1.f);
    float4 b  = ((const float4*)bg)[lane];
    float4 b2 = ((const float4*)bc)[lane];
    float4* oc = (float4*)(g_hcat + (size_t)gw * C3);
    oc[lane]      = make_float4(ag0 * inv + b.x,  ag1 * inv + b.y,
                                ag2 * inv + b.z,  ag3 * inv + b.w);
    oc[lane + 32] = make_float4(ac0 + b2.x, ac1 + b2.y, ac2 + b2.z, ac3 + b2.w);
    ((float4*)(g_sage + (size_t)gw * HD))[lane] =
        make_float4(ax0 * ci, ax1 * ci, ax2 * ci, ax3 * ci);
}

// ---------------- BatchNorm stats ------------------------------------------
__global__ void bn_zero()
{
    int t = threadIdx.x;
    if (t < C3) { g_sums[t] = 0.f; g_sumsq[t] = 0.f; }
}

__global__ void bn_stats(int N)
{
    int c = blockIdx.x * 32 + threadIdx.x;
    float s = 0.f, q = 0.f;
    for (int r = blockIdx.y * blockDim.y + threadIdx.y; r < N; r += gridDim.y * blockDim.y) {
        float v = g_hcat[(size_t)r * C3 + c];
        s += v; q += v * v;
    }
    __shared__ float sh[8][33], shq[8][33];
    sh[threadIdx.y][threadIdx.x] = s;
    shq[threadIdx.y][threadIdx.x] = q;
    __syncthreads();
    if (threadIdx.y == 0) {
        #pragma unroll
        for (int j = 1; j < 8; j++) { s += sh[j][threadIdx.x]; q += shq[j][threadIdx.x]; }
        atomicAdd(&g_sums[c], s);
        atomicAdd(&g_sumsq[c], q);
    }
}

__global__ void bn_scale(const float* __restrict__ gamma,
                         const float* __restrict__ beta, int N)
{
    int c = threadIdx.x;
    if (c >= C3) return;
    float invN = 1.f / (float)N;
    float mu  = g_sums[c] * invN;
    float var = g_sumsq[c] * invN - mu * mu;
    float sc  = gamma[c] * rsqrtf(var + 1e-5f);
    g_scale[c] = sc;
    g_shift[c] = beta[c] - mu * sc;
}

// ---------------- proven 128x64-tile fp32 GEMM, 8x4 micro-tile --------------
// C[M,Nc] = act(A[M,K]) @ B[K,Nc] (+bias) (+Dadd)
// MODE 0: identity ; MODE 1: relu(A) ; MODE 2: relu(A*g_scale[k]+g_shift[k])
template<int MODE>
__global__ void __launch_bounds__(256) gemm_k(
    const float* __restrict__ Aext, int Atag, int Aoff, int lda,
    const float* __restrict__ Bext, int Btag, int ldb,
    float* __restrict__ Cext, int Ctag, int Coff, int ldc,
    int M, int Nc, int K,
    const float* __restrict__ bias,
    int Dtag, int Doff, int ldd)
{
    const float* A = Aext ? Aext : (const float*)(buf(Atag) + Aoff);
    const float* B = Bext ? Bext : (const float*)buf(Btag);
    float*       C = Cext ? Cext : (buf(Ctag) + Coff);
    const float* Dadd = (Dtag >= 0) ? (const float*)(buf(Dtag) + Doff) : nullptr;

    __shared__ float As[16][128];
    __shared__ float Bs[16][64];
    const int t = threadIdx.x;
    const int rowBase = blockIdx.x * 128;
    const int colBase = blockIdx.y * 64;
    const int ty = t >> 4, tx = t & 15;
    float acc[8][4];
    #pragma unroll
    for (int m = 0; m < 8; m++)
        #pragma unroll
        for (int n = 0; n < 4; n++) acc[m][n] = 0.f;

    for (int k0 = 0; k0 < K; k0 += 16) {
        #pragma unroll
        for (int i = 0; i < 2; i++) {
            int idx = t + i * 256;
            int r   = idx >> 2;
            int kc  = (idx & 3) << 2;
            int grow = rowBase + r;
            float4 v = make_float4(0.f, 0.f, 0.f, 0.f);
            if (grow < M) v = *(const float4*)(A + (size_t)grow * lda + k0 + kc);
            if (MODE == 1) {
                v.x = fmaxf(v.x, 0.f); v.y = fmaxf(v.y, 0.f);
                v.z = fmaxf(v.z, 0.f); v.w = fmaxf(v.w, 0.f);
            }
            if (MODE == 2) {
                v.x = fmaxf(v.x * g_scale[k0 + kc + 0] + g_shift[k0 + kc + 0], 0.f);
                v.y = fmaxf(v.y * g_scale[k0 + kc + 1] + g_shift[k0 + kc + 1], 0.f);
                v.z = fmaxf(v.z * g_scale[k0 + kc + 2] + g_shift[k0 + kc + 2], 0.f);
                v.w = fmaxf(v.w * g_scale[k0 + kc + 3] + g_shift[k0 + kc + 3], 0.f);
            }
            As[kc + 0][r] = v.x; As[kc + 1][r] = v.y;
            As[kc + 2][r] = v.z; As[kc + 3][r] = v.w;
        }
        {
            int kr = t >> 4;
            int c4 = (t & 15) << 2;
            int gc = colBase + c4;
            float4 v = make_float4(0.f, 0.f, 0.f, 0.f);
            if (gc < Nc) v = *(const float4*)(B + (size_t)(k0 + kr) * ldb + gc);
            *(float4*)&Bs[kr][c4] = v;
        }
        __syncthreads();
        #pragma unroll
        for (int k = 0; k < 16; k++) {
            float a[8], b[4];
            #pragma unroll
            for (int m = 0; m < 8; m++) a[m] = As[k][ty * 8 + m];
            #pragma unroll
            for (int n = 0; n < 4; n++) b[n] = Bs[k][tx * 4 + n];
            #pragma unroll
            for (int m = 0; m < 8; m++)
                #pragma unroll
                for (int n = 0; n < 4; n++)
                    acc[m][n] = fmaf(a[m], b[n], acc[m][n]);
        }
        __syncthreads();
    }
    #pragma unroll
    for (int m = 0; m < 8; m++) {
        int gr = rowBase + ty * 8 + m;
        if (gr >= M) continue;
        #pragma unroll
        for (int n = 0; n < 4; n++) {
            int gc = colBase + tx * 4 + n;
            if (gc >= Nc) continue;
            float v = acc[m][n];
            if (bias) v += bias[gc];
            if (Dadd) v += Dadd[(size_t)gr * ldd + gc];
            C[(size_t)gr * ldc + gc] = v;
        }
    }
}

// ---------------- launch ----------------------------------------------------
extern "C" void kernel_launch(void* const* d_in, const int* in_sizes, int n_in,
                              void* d_out, int out_size)
{
    const float* x        = (const float*)d_in[0];
    const void*  ei       = d_in[1];
    const float* W_gat    = (const float*)d_in[2];
    const float* att_src  = (const float*)d_in[3];
    const float* att_dst  = (const float*)d_in[4];
    const float* b_gat    = (const float*)d_in[5];
    const float* W_gcn    = (const float*)d_in[6];
    const float* b_gcn    = (const float*)d_in[7];
    const float* W_sage_l = (const float*)d_in[8];
    const float* b_sage_l = (const float*)d_in[9];
    const float* W_sage_r = (const float*)d_in[10];
    const float* W1       = (const float*)d_in[11];
    const float* b1       = (const float*)d_in[12];
    const float* W2       = (const float*)d_in[13];
    const float* b2       = (const float*)d_in[14];
    const float* W3       = (const float*)d_in[15];
    const float* b3       = (const float*)d_in[16];
    const float* gamma    = (const float*)d_in[17];
    const float* beta     = (const float*)d_in[18];
    float* out = (float*)d_out;

    int N = in_sizes[0] / FIN;
    int E = in_sizes[1] / 2;

    // 0) detect edge_index storage width (int32 vs int64); pack node-GEMM B
    detect_idx<<<1, 128>>>(ei, E);
    pack_w<<<(FIN * C3 + 255) / 256, 256>>>(W_gat, W_gcn, W_sage_r);

    int gm = (N + 127) / 128;

    // 1) H = x @ [W_gat | W_gcn | W_sage_r]  (one merged GEMM, Nc=384, 6 col-tiles)
    gemm_k<0><<<dim3(gm, 6), 256>>>(x, TAG_NONE, 0, FIN, nullptr, TAG_WCAT, C3,
                                    nullptr, TAG_H, 0, C3, N, C3, FIN,
                                    nullptr, TAG_NONE, 0, 0);

    // 2-6) graph aggregation via CSR gather
    node_init<<<(N + 7) / 8, 256>>>(att_src, att_dst, N);
    edge_pass1<<<(E + 255) / 256, 256>>>(ei, E);
    node_seed<<<(N + 255) / 256, 256>>>(N);
    scan_cnt<<<1, 1024>>>(N, E);
    edge_fill<<<(E + 255) / 256, 256>>>(ei, E);
    gather<<<(N + 7) / 8, 256>>>(x, b_gat, b_gcn, N);

    // 7) sage: hcat[:,256:384] = mean @ W_sage_l + b_sage_l + (x@W_sage_r)
    gemm_k<0><<<dim3(gm, 2), 256>>>(nullptr, TAG_SAGE, 0, HD, W_sage_l, TAG_NONE, HD,
                                    nullptr, TAG_HCAT, 256, C3, N, HD, HD,
                                    b_sage_l, TAG_H, 256, C3);

    // 8-9) batchnorm statistics -> per-channel scale/shift
    bn_zero<<<1, 384>>>();
    dim3 bs(32, 8), bg(C3 / 32, 128);
    bn_stats<<<bg, bs>>>(N);
    bn_scale<<<1, 384>>>(gamma, beta, N);

    // 10-12) MLP (BN affine + relu fused into W1 A-load; relu fused into later loads)
    gemm_k<2><<<dim3(gm, 4), 256>>>(nullptr, TAG_HCAT, 0, C3, W1, TAG_NONE, H1D,
                                    nullptr, TAG_H1, 0, H1D, N, H1D, C3,
                                    b1, TAG_NONE, 0, 0);
    gemm_k<1><<<dim3(gm, 2), 256>>>(nullptr, TAG_H1, 0, H1D, W2, TAG_NONE, HD,
                                    nullptr, TAG_H2, 0, HD, N, HD, H1D,
                                    b2, TAG_NONE, 0, 0);
    gemm_k<1><<<dim3(gm, 1), 256>>>(nullptr, TAG_H2, 0, HD, W3, TAG_NONE, OUTD,
                                    out, TAG_NONE, 0, OUTD, N, OUTD, HD,
                                    b3, TAG_NONE, 0, 0);
}